// round 6
// baseline (speedup 1.0000x reference)
#include <cuda_runtime.h>
#include <cuda_bf16.h>
#include <cstdint>

#define DDIM 4096

// Scratch (static __device__ arrays: allocation-free per harness rules)
__device__ int8_t g_q[(size_t)DDIM * DDIM];   // quantized activations, int8 in [-8,7]
__device__ int8_t g_w[(size_t)DDIM * DDIM];   // int4 weights as int8
__device__ float  g_sx[DDIM];                 // per-row activation scales (max/7)

// ---------------- PTX utility ----------------
__device__ __forceinline__ uint32_t smem_u32(const void* p) {
    uint32_t a;
    asm("{ .reg .u64 t; cvta.to.shared.u64 t, %1; cvt.u32.u64 %0, t; }" : "=r"(a) : "l"(p));
    return a;
}
__device__ __forceinline__ void cp16(uint32_t dst, const void* src) {
    asm volatile("cp.async.cg.shared.global [%0], [%1], 16;\n" :: "r"(dst), "l"(src));
}
#define CP_COMMIT() asm volatile("cp.async.commit_group;\n" ::: "memory")

__device__ __forceinline__ void ldsm4(uint32_t* r, uint32_t addr) {
    asm volatile("ldmatrix.sync.aligned.m8n8.x4.shared.b16 {%0,%1,%2,%3}, [%4];\n"
                 : "=r"(r[0]), "=r"(r[1]), "=r"(r[2]), "=r"(r[3]) : "r"(addr));
}
__device__ __forceinline__ void imma(int* c, const uint32_t* a, uint32_t b0, uint32_t b1) {
    asm volatile(
        "mma.sync.aligned.m16n8k32.row.col.s32.s8.s8.s32 "
        "{%0,%1,%2,%3}, {%4,%5,%6,%7}, {%8,%9}, {%0,%1,%2,%3};\n"
        : "+r"(c[0]), "+r"(c[1]), "+r"(c[2]), "+r"(c[3])
        : "r"(a[0]), "r"(a[1]), "r"(a[2]), "r"(a[3]), "r"(b0), "r"(b1));
}

// ============================================================================
// Kernel 1: blockwise FWHT(256) + per-row absmax + int4 quantize -> int8
// grid = 4096 rows, block = 512 (16 warps; warp w owns 256-block w)
// ============================================================================
__global__ void __launch_bounds__(512) had_quant_kernel(const float* __restrict__ x) {
    const int row = blockIdx.x;
    const int t = threadIdx.x;
    const int w = t >> 5, l = t & 31;

    const float* xr = x + (size_t)row * DDIM + w * 256;
    float v[8];
#pragma unroll
    for (int j = 0; j < 8; j++) v[j] = xr[j * 32 + l];

    // FWHT stages over lane bits 0..4
#pragma unroll
    for (int s = 0; s < 5; s++) {
        const int m = 1 << s;
        const bool hi = (l & m) != 0;
#pragma unroll
        for (int j = 0; j < 8; j++) {
            float p = __shfl_xor_sync(0xFFFFFFFFu, v[j], m);
            v[j] = hi ? (p - v[j]) : (v[j] + p);
        }
    }
    // FWHT stages over register bits 5..7 (index j)
#pragma unroll
    for (int s = 0; s < 3; s++) {
        const int m = 1 << s;
#pragma unroll
        for (int j = 0; j < 8; j++) {
            if (!(j & m)) {
                float a = v[j], b = v[j | m];
                v[j] = a + b;
                v[j | m] = a - b;
            }
        }
    }

    float amax = 0.0f;
#pragma unroll
    for (int j = 0; j < 8; j++) {
        v[j] *= 0.0625f;  // 1/sqrt(256)
        amax = fmaxf(amax, fabsf(v[j]));
    }
#pragma unroll
    for (int o = 16; o > 0; o >>= 1)
        amax = fmaxf(amax, __shfl_xor_sync(0xFFFFFFFFu, amax, o));

    __shared__ float smax[16];
    if (l == 0) smax[w] = amax;
    __syncthreads();
    if (t == 0) {
        float mx = smax[0];
#pragma unroll
        for (int i = 1; i < 16; i++) mx = fmaxf(mx, smax[i]);
        float sx = mx / 7.0f;
        smax[0] = sx;
        g_sx[row] = sx;
    }
    __syncthreads();
    const float sx = smax[0];

    int8_t* qr = g_q + (size_t)row * DDIM + w * 256;
#pragma unroll
    for (int j = 0; j < 8; j++) {
        float qv = rintf(v[j] / sx);              // round-half-even, matches jnp.round
        qv = fminf(fmaxf(qv, -8.0f), 7.0f);
        qr[j * 32 + l] = (int8_t)(int)qv;
    }
}

// ============================================================================
// Kernel 2: weight int32 -> int8 (values in [-7,7])
// ============================================================================
__global__ void __launch_bounds__(256) wconv_kernel(const int* __restrict__ wi) {
    const size_t i = ((size_t)blockIdx.x * blockDim.x + threadIdx.x) * 4;
    int4 a = *(const int4*)(wi + i);
    char4 c = make_char4((char)a.x, (char)a.y, (char)a.z, (char)a.w);
    *(char4*)(g_w + i) = c;
}

// ============================================================================
// Kernel 3: int8 mma.sync GEMM, BM=128 x BN=128 x BK=64, 4-stage cp.async,
//           fused dequant epilogue. 256 threads = 8 warps (4 M x 2 N),
//           warp tile 32x64 via m16n8k32 IMMA.
// __launch_bounds__(256,1): 255-reg budget so the 64 accumulators stay in
// registers (the (256,2) 128-reg cap spilled them -> ~16k cyc/iter).
// SMEM rows padded to 80B: ldmatrix 16B row-starts land on banks
// {0,20,8,28,16,4,24,12} (x4B) -> conflict-free without swizzle.
// ============================================================================
#define BM 128
#define BN 128
#define BK 64
#define KITERS (DDIM / BK)          // 64
#define STAGES 4
#define ROWB 80                     // padded smem row stride (bytes)
#define TILEB (128 * ROWB)          // 10240 per operand tile
#define STAGEB (2 * TILEB)          // A + B
#define SMEMB (STAGES * STAGEB)     // 81920

__global__ void __launch_bounds__(256, 1)
gemm_kernel(float* __restrict__ out, const float* __restrict__ wsc,
            const float* __restrict__ bias) {
    extern __shared__ char smem[];
    const uint32_t sb = smem_u32(smem);
    const int t = threadIdx.x;
    const int lane = t & 31, wid = t >> 5;
    const int mrow = blockIdx.y * BM;
    const int ncol = blockIdx.x * BN;
    const int wm = (wid & 3) * 32;      // warp M offset in tile
    const int wn = (wid >> 2) * 64;     // warp N offset in tile

    const int8_t* gA = g_q + (size_t)mrow * DDIM;
    const int8_t* gB = g_w + (size_t)ncol * DDIM;

    // per-thread cp.async chunk mapping: 512 16B chunks per operand, 2 each
    const int ch0 = t * 2;

    // ldmatrix per-lane address components
    const int arow = lane & 15;                     // A: rows 0..15 of 16x32 frag
    const int ahi  = ((lane >> 4) & 1) * 16;        // A: lo/hi 16B of 32B k-step
    const int brow = (lane & 7) + ((lane >> 4) & 1) * 8;  // B: n-rows (2 tiles)
    const int bhi  = ((lane >> 3) & 1) * 16;        // B: lo/hi 16B

    int acc[2][8][4];
#pragma unroll
    for (int mt = 0; mt < 2; mt++)
#pragma unroll
        for (int nt = 0; nt < 8; nt++)
#pragma unroll
            for (int i = 0; i < 4; i++) acc[mt][nt][i] = 0;

    // ---- prologue: stages 0..2 ----
#pragma unroll
    for (int s = 0; s < 3; s++) {
        const uint32_t abase = sb + s * STAGEB;
        const uint32_t bbase = abase + TILEB;
#pragma unroll
        for (int u = 0; u < 2; u++) {
            const int cc = ch0 + u, r = cc >> 2, c = cc & 3;
            cp16(abase + r * ROWB + c * 16, gA + (size_t)r * DDIM + s * BK + c * 16);
        }
#pragma unroll
        for (int u = 0; u < 2; u++) {
            const int cc = ch0 + u, r = cc >> 2, c = cc & 3;
            cp16(bbase + r * ROWB + c * 16, gB + (size_t)r * DDIM + s * BK + c * 16);
        }
        CP_COMMIT();
    }

    // ---- main loop ----
    for (int it = 0; it < KITERS; it++) {
        __syncthreads();  // all warps done with slot (it+3)%4 == (it-1)%4
        if (it + 3 < KITERS) {
            const int slot = (it + 3) & 3;
            const int kb = (it + 3) * BK;
            const uint32_t abase = sb + slot * STAGEB;
            const uint32_t bbase = abase + TILEB;
#pragma unroll
            for (int u = 0; u < 2; u++) {
                const int cc = ch0 + u, r = cc >> 2, c = cc & 3;
                cp16(abase + r * ROWB + c * 16, gA + (size_t)r * DDIM + kb + c * 16);
            }
#pragma unroll
            for (int u = 0; u < 2; u++) {
                const int cc = ch0 + u, r = cc >> 2, c = cc & 3;
                cp16(bbase + r * ROWB + c * 16, gB + (size_t)r * DDIM + kb + c * 16);
            }
        }
        CP_COMMIT();  // empty group near tail keeps the count uniform
        asm volatile("cp.async.wait_group 3;\n" ::: "memory");
        __syncthreads();  // stage `it` visible to all warps

        const uint32_t abase = sb + (it & 3) * STAGEB;
        const uint32_t bbase = abase + TILEB;
#pragma unroll
        for (int ks = 0; ks < 2; ks++) {
            uint32_t af[2][4];
#pragma unroll
            for (int mt = 0; mt < 2; mt++)
                ldsm4(af[mt], abase + (wm + mt * 16 + arow) * ROWB + ks * 32 + ahi);
            uint32_t bf[4][4];
#pragma unroll
            for (int p = 0; p < 4; p++)
                ldsm4(bf[p], bbase + (wn + p * 16 + brow) * ROWB + ks * 32 + bhi);
#pragma unroll
            for (int mt = 0; mt < 2; mt++)
#pragma unroll
                for (int nt = 0; nt < 8; nt++)
                    imma(acc[mt][nt], af[mt], bf[nt >> 1][(nt & 1) * 2],
                         bf[nt >> 1][(nt & 1) * 2 + 1]);
        }
    }

    // ---- fused dequant epilogue ----
    const int g = lane >> 2, tg = lane & 3;
#pragma unroll
    for (int mt = 0; mt < 2; mt++) {
        const int r0 = mrow + wm + mt * 16 + g;
        const float sx0 = g_sx[r0];
        const float sx1 = g_sx[r0 + 8];
        float* o0 = out + (size_t)r0 * DDIM + ncol + wn;
        float* o1 = o0 + (size_t)8 * DDIM;
#pragma unroll
        for (int nt = 0; nt < 8; nt++) {
            const int co = nt * 8 + tg * 2;
            const int col = ncol + wn + co;
            const float w0 = __ldg(wsc + col), w1 = __ldg(wsc + col + 1);
            const float b0 = __ldg(bias + col), b1 = __ldg(bias + col + 1);
            float2 v0, v1;
            v0.x = (float)acc[mt][nt][0] * sx0 * w0 + b0;
            v0.y = (float)acc[mt][nt][1] * sx0 * w1 + b1;
            v1.x = (float)acc[mt][nt][2] * sx1 * w0 + b0;
            v1.y = (float)acc[mt][nt][3] * sx1 * w1 + b1;
            *(float2*)(o0 + co) = v0;
            *(float2*)(o1 + co) = v1;
        }
    }
}

// ============================================================================
extern "C" void kernel_launch(void* const* d_in, const int* in_sizes, int n_in,
                              void* d_out, int out_size) {
    const float* x    = (const float*)d_in[0];
    const int*   wi   = (const int*)d_in[1];
    const float* wsc  = (const float*)d_in[2];
    const float* bias = (const float*)d_in[3];
    float* out = (float*)d_out;
    (void)in_sizes; (void)n_in; (void)out_size;

    cudaFuncSetAttribute(gemm_kernel, cudaFuncAttributeMaxDynamicSharedMemorySize, SMEMB);

    had_quant_kernel<<<DDIM, 512>>>(x);
    wconv_kernel<<<(DDIM * (size_t)DDIM) / 4 / 256, 256>>>(wi);
    gemm_kernel<<<dim3(DDIM / BN, DDIM / BM), 256, SMEMB>>>(out, wsc, bias);
}

// round 9
// speedup vs baseline: 1.1852x; 1.1852x over previous
#include <cuda_runtime.h>
#include <cuda_bf16.h>
#include <cstdint>

#define DDIM 4096

// Scratch (static __device__ arrays: allocation-free per harness rules)
__device__ int8_t g_q[(size_t)DDIM * DDIM];   // quantized activations, int8 in [-8,7]
__device__ int8_t g_w[(size_t)DDIM * DDIM];   // int4 weights as int8
__device__ float  g_sx[DDIM];                 // per-row activation scales (max/7)

// ---------------- PTX utility ----------------
__device__ __forceinline__ uint32_t smem_u32(const void* p) {
    uint32_t a;
    asm("{ .reg .u64 t; cvta.to.shared.u64 t, %1; cvt.u32.u64 %0, t; }" : "=r"(a) : "l"(p));
    return a;
}
__device__ __forceinline__ void cp16(uint32_t dst, const void* src) {
    asm volatile("cp.async.cg.shared.global [%0], [%1], 16;\n" :: "r"(dst), "l"(src));
}
#define CP_COMMIT() asm volatile("cp.async.commit_group;\n" ::: "memory")

__device__ __forceinline__ void barx(int id, int cnt) {
    asm volatile("bar.sync %0, %1;" :: "r"(id), "r"(cnt) : "memory");
}
__device__ __forceinline__ void ldsm4(uint32_t* r, uint32_t addr) {
    asm volatile("ldmatrix.sync.aligned.m8n8.x4.shared.b16 {%0,%1,%2,%3}, [%4];\n"
                 : "=r"(r[0]), "=r"(r[1]), "=r"(r[2]), "=r"(r[3]) : "r"(addr));
}
__device__ __forceinline__ void imma(int* c, const uint32_t* a, uint32_t b0, uint32_t b1) {
    asm volatile(
        "mma.sync.aligned.m16n8k32.row.col.s32.s8.s8.s32 "
        "{%0,%1,%2,%3}, {%4,%5,%6,%7}, {%8,%9}, {%0,%1,%2,%3};\n"
        : "+r"(c[0]), "+r"(c[1]), "+r"(c[2]), "+r"(c[3])
        : "r"(a[0]), "r"(a[1]), "r"(a[2]), "r"(a[3]), "r"(b0), "r"(b1));
}
__device__ __forceinline__ uint32_t lds32(uint32_t addr) {
    uint32_t v;
    asm volatile("ld.shared.b32 %0, [%1];" : "=r"(v) : "r"(addr));
    return v;
}

// ============================================================================
// Kernel 1: blockwise FWHT(256) + per-row absmax + int4 quantize -> int8
// ============================================================================
__global__ void __launch_bounds__(512) had_quant_kernel(const float* __restrict__ x) {
    const int row = blockIdx.x;
    const int t = threadIdx.x;
    const int w = t >> 5, l = t & 31;

    const float* xr = x + (size_t)row * DDIM + w * 256;
    float v[8];
#pragma unroll
    for (int j = 0; j < 8; j++) v[j] = xr[j * 32 + l];

#pragma unroll
    for (int s = 0; s < 5; s++) {
        const int m = 1 << s;
        const bool hi = (l & m) != 0;
#pragma unroll
        for (int j = 0; j < 8; j++) {
            float p = __shfl_xor_sync(0xFFFFFFFFu, v[j], m);
            v[j] = hi ? (p - v[j]) : (v[j] + p);
        }
    }
#pragma unroll
    for (int s = 0; s < 3; s++) {
        const int m = 1 << s;
#pragma unroll
        for (int j = 0; j < 8; j++) {
            if (!(j & m)) {
                float a = v[j], b = v[j | m];
                v[j] = a + b;
                v[j | m] = a - b;
            }
        }
    }

    float amax = 0.0f;
#pragma unroll
    for (int j = 0; j < 8; j++) {
        v[j] *= 0.0625f;  // 1/sqrt(256)
        amax = fmaxf(amax, fabsf(v[j]));
    }
#pragma unroll
    for (int o = 16; o > 0; o >>= 1)
        amax = fmaxf(amax, __shfl_xor_sync(0xFFFFFFFFu, amax, o));

    __shared__ float smax[16];
    if (l == 0) smax[w] = amax;
    __syncthreads();
    if (t == 0) {
        float mx = smax[0];
#pragma unroll
        for (int i = 1; i < 16; i++) mx = fmaxf(mx, smax[i]);
        float sx = mx / 7.0f;
        smax[0] = sx;
        g_sx[row] = sx;
    }
    __syncthreads();
    const float sx = smax[0];

    int8_t* qr = g_q + (size_t)row * DDIM + w * 256;
#pragma unroll
    for (int j = 0; j < 8; j++) {
        float qv = rintf(v[j] / sx);              // round-half-even, matches jnp.round
        qv = fminf(fmaxf(qv, -8.0f), 7.0f);
        qr[j * 32 + l] = (int8_t)(int)qv;
    }
}

// ============================================================================
// Kernel 2: weight int32 -> int8 (values in [-7,7])
// ============================================================================
__global__ void __launch_bounds__(256) wconv_kernel(const int* __restrict__ wi) {
    const size_t i = ((size_t)blockIdx.x * blockDim.x + threadIdx.x) * 4;
    int4 a = *(const int4*)(wi + i);
    char4 c = make_char4((char)a.x, (char)a.y, (char)a.z, (char)a.w);
    *(char4*)(g_w + i) = c;
}

// ============================================================================
// Kernel 3: dual-pipe int8 GEMM. CTA tile 128x128, K chunk 64, 64 K-iters.
//   Warps 0-7  (256 thr): legacy tensor pipe (mma.sync IMMA), output cols 0-63.
//   Warps 8-11 (128 thr): ALU pipe (dp4a), output cols 64-127.
// The two groups have independent cp.async pipelines, smem buffers and named
// barriers so the tensor-compat pipe and the IMAD pipe run concurrently.
// SMEM rows padded to 80B: stride 20 words mod 32 banks -> conflict-free for
// both ldmatrix row-starts and dp4a strided word reads.
// ============================================================================
#define BM 128
#define BN 128
#define BK 64
#define KITERS (DDIM / BK)          // 64
#define ROWB 80                     // padded smem row stride (bytes)
#define I_ATILEB (128 * ROWB)       // 10240: A tile 128x64
#define I_BTILEB (64 * ROWB)        // 5120:  B tile 64x64 (IMMA half)
#define I_STAGEB (I_ATILEB + I_BTILEB)   // 15360
#define D_OFF (4 * I_STAGEB)        // 61440: dp4a region start
#define D_ATILEB (128 * ROWB)       // 10240
#define D_BTILEB (64 * ROWB)        // 5120
#define D_STAGEB (D_ATILEB + D_BTILEB)   // 15360
#define SMEMB (D_OFF + 4 * D_STAGEB)     // 122880

__global__ void __launch_bounds__(384, 1)
gemm_kernel(float* __restrict__ out, const float* __restrict__ wsc,
            const float* __restrict__ bias) {
    extern __shared__ char smem[];
    const uint32_t sb = smem_u32(smem);
    const int t = threadIdx.x;
    const int mrow = blockIdx.y * BM;
    const int ncol = blockIdx.x * BN;

    if (t < 256) {
        // ================= IMMA group: cols [ncol, ncol+64) =================
        const int lane = t & 31, wid = t >> 5;
        const int wm = (wid & 3) * 32;      // warp M offset
        const int wn = (wid >> 2) * 32;     // warp N offset (0 or 32)

        const int8_t* gA = g_q + (size_t)mrow * DDIM;
        const int8_t* gB = g_w + (size_t)ncol * DDIM;

        // A: 512 chunks -> 2/thread; B: 256 chunks -> 1/thread
        const int ar0 = (t * 2) >> 2, ac0 = (t * 2) & 3;   // ac0 in {0,2}
        const int br = t >> 2, bc = t & 3;

        const int arow = lane & 15;
        const int ahi  = ((lane >> 4) & 1) * 16;
        const int brow = (lane & 7) + ((lane >> 4) & 1) * 8;
        const int bhi  = ((lane >> 3) & 1) * 16;

        int acc[2][4][4];
#pragma unroll
        for (int mt = 0; mt < 2; mt++)
#pragma unroll
            for (int nt = 0; nt < 4; nt++)
#pragma unroll
                for (int i = 0; i < 4; i++) acc[mt][nt][i] = 0;

#pragma unroll
        for (int s = 0; s < 3; s++) {
            const uint32_t ab = sb + s * I_STAGEB;
            cp16(ab + ar0 * ROWB + ac0 * 16, gA + (size_t)ar0 * DDIM + s * BK + ac0 * 16);
            cp16(ab + ar0 * ROWB + (ac0 + 1) * 16, gA + (size_t)ar0 * DDIM + s * BK + (ac0 + 1) * 16);
            cp16(ab + I_ATILEB + br * ROWB + bc * 16, gB + (size_t)br * DDIM + s * BK + bc * 16);
            CP_COMMIT();
        }

        for (int it = 0; it < KITERS; it++) {
            barx(1, 256);
            if (it + 3 < KITERS) {
                const int slot = (it + 3) & 3;
                const int kb = (it + 3) * BK;
                const uint32_t ab = sb + slot * I_STAGEB;
                cp16(ab + ar0 * ROWB + ac0 * 16, gA + (size_t)ar0 * DDIM + kb + ac0 * 16);
                cp16(ab + ar0 * ROWB + (ac0 + 1) * 16, gA + (size_t)ar0 * DDIM + kb + (ac0 + 1) * 16);
                cp16(ab + I_ATILEB + br * ROWB + bc * 16, gB + (size_t)br * DDIM + kb + bc * 16);
            }
            CP_COMMIT();
            asm volatile("cp.async.wait_group 3;\n" ::: "memory");
            barx(1, 256);

            const uint32_t ab = sb + (it & 3) * I_STAGEB;
            const uint32_t bb = ab + I_ATILEB;
#pragma unroll
            for (int ks = 0; ks < 2; ks++) {
                uint32_t af[2][4];
#pragma unroll
                for (int mt = 0; mt < 2; mt++)
                    ldsm4(af[mt], ab + (wm + mt * 16 + arow) * ROWB + ks * 32 + ahi);
                uint32_t bf[2][4];
#pragma unroll
                for (int p = 0; p < 2; p++)
                    ldsm4(bf[p], bb + (wn + p * 16 + brow) * ROWB + ks * 32 + bhi);
#pragma unroll
                for (int mt = 0; mt < 2; mt++)
#pragma unroll
                    for (int nt = 0; nt < 4; nt++)
                        imma(acc[mt][nt], af[mt], bf[nt >> 1][(nt & 1) * 2],
                             bf[nt >> 1][(nt & 1) * 2 + 1]);
            }
        }

        // fused dequant epilogue (cols 0..63 of the CTA tile)
        const int g = lane >> 2, tg = lane & 3;
#pragma unroll
        for (int mt = 0; mt < 2; mt++) {
            const int r0 = mrow + wm + mt * 16 + g;
            const float sx0 = g_sx[r0];
            const float sx1 = g_sx[r0 + 8];
            float* o0 = out + (size_t)r0 * DDIM + ncol + wn;
            float* o1 = o0 + (size_t)8 * DDIM;
#pragma unroll
            for (int nt = 0; nt < 4; nt++) {
                const int co = nt * 8 + tg * 2;
                const int col = ncol + wn + co;
                const float w0 = __ldg(wsc + col), w1 = __ldg(wsc + col + 1);
                const float b0 = __ldg(bias + col), b1 = __ldg(bias + col + 1);
                float2 v0, v1;
                v0.x = (float)acc[mt][nt][0] * sx0 * w0 + b0;
                v0.y = (float)acc[mt][nt][1] * sx0 * w1 + b1;
                v1.x = (float)acc[mt][nt][2] * sx1 * w0 + b0;
                v1.y = (float)acc[mt][nt][3] * sx1 * w1 + b1;
                *(float2*)(o0 + co) = v0;
                *(float2*)(o1 + co) = v1;
            }
        }
    } else {
        // ================= dp4a group: cols [ncol+64, ncol+128) =============
        const int t2 = t - 256;             // 0..127
        const int tx = t2 & 7;              // col group
        const int ty = t2 >> 3;             // row group 0..15

        const int8_t* gA = g_q + (size_t)mrow * DDIM;
        const int8_t* gB = g_w + (size_t)(ncol + 64) * DDIM;

        // A: 512 chunks -> 4/thread; B: 256 chunks -> 2/thread
        const int ar0 = t2;                 // rows t2*4.. no: chunk cc = t2*4+u
        (void)ar0;

        int acc[8][8];
#pragma unroll
        for (int jj = 0; jj < 8; jj++)
#pragma unroll
            for (int kk = 0; kk < 8; kk++) acc[jj][kk] = 0;

        const uint32_t dbase = sb + D_OFF;

#pragma unroll
        for (int s = 0; s < 3; s++) {
            const uint32_t ab = dbase + s * D_STAGEB;
#pragma unroll
            for (int u = 0; u < 4; u++) {
                const int cc = t2 * 4 + u, r = cc >> 2, c = cc & 3;
                cp16(ab + r * ROWB + c * 16, gA + (size_t)r * DDIM + s * BK + c * 16);
            }
#pragma unroll
            for (int u = 0; u < 2; u++) {
                const int cc = t2 * 2 + u, r = cc >> 2, c = cc & 3;
                cp16(ab + D_ATILEB + r * ROWB + c * 16, gB + (size_t)r * DDIM + s * BK + c * 16);
            }
            CP_COMMIT();
        }

        for (int it = 0; it < KITERS; it++) {
            barx(2, 128);
            if (it + 3 < KITERS) {
                const int slot = (it + 3) & 3;
                const int kb = (it + 3) * BK;
                const uint32_t ab = dbase + slot * D_STAGEB;
#pragma unroll
                for (int u = 0; u < 4; u++) {
                    const int cc = t2 * 4 + u, r = cc >> 2, c = cc & 3;
                    cp16(ab + r * ROWB + c * 16, gA + (size_t)r * DDIM + kb + c * 16);
                }
#pragma unroll
                for (int u = 0; u < 2; u++) {
                    const int cc = t2 * 2 + u, r = cc >> 2, c = cc & 3;
                    cp16(ab + D_ATILEB + r * ROWB + c * 16, gB + (size_t)r * DDIM + kb + c * 16);
                }
            }
            CP_COMMIT();
            asm volatile("cp.async.wait_group 3;\n" ::: "memory");
            barx(2, 128);

            const uint32_t ab = dbase + (it & 3) * D_STAGEB;
            const uint32_t bb = ab + D_ATILEB;
#pragma unroll 4
            for (int k4 = 0; k4 < 16; k4++) {
                uint32_t a[8], b[8];
#pragma unroll
                for (int jj = 0; jj < 8; jj++)
                    a[jj] = lds32(ab + (ty + 16 * jj) * ROWB + k4 * 4);
#pragma unroll
                for (int kk = 0; kk < 8; kk++)
                    b[kk] = lds32(bb + (tx + 8 * kk) * ROWB + k4 * 4);
#pragma unroll
                for (int jj = 0; jj < 8; jj++)
#pragma unroll
                    for (int kk = 0; kk < 8; kk++)
                        acc[jj][kk] = __dp4a((int)a[jj], (int)b[kk], acc[jj][kk]);
            }
        }

        // fused dequant epilogue (cols 64..127 of the CTA tile)
#pragma unroll
        for (int jj = 0; jj < 8; jj++) {
            const int r = mrow + ty + 16 * jj;
            const float sx = g_sx[r];
            float* o = out + (size_t)r * DDIM + ncol + 64;
#pragma unroll
            for (int kk = 0; kk < 8; kk++) {
                const int c = tx + 8 * kk;
                const int col = ncol + 64 + c;
                o[c] = (float)acc[jj][kk] * sx * __ldg(wsc + col) + __ldg(bias + col);
            }
        }
    }
}

// ============================================================================
extern "C" void kernel_launch(void* const* d_in, const int* in_sizes, int n_in,
                              void* d_out, int out_size) {
    const float* x    = (const float*)d_in[0];
    const int*   wi   = (const int*)d_in[1];
    const float* wsc  = (const float*)d_in[2];
    const float* bias = (const float*)d_in[3];
    float* out = (float*)d_out;
    (void)in_sizes; (void)n_in; (void)out_size;

    cudaFuncSetAttribute(gemm_kernel, cudaFuncAttributeMaxDynamicSharedMemorySize, SMEMB);

    had_quant_kernel<<<DDIM, 512>>>(x);
    wconv_kernel<<<(DDIM * (size_t)DDIM) / 4 / 256, 256>>>(wi);
    gemm_kernel<<<dim3(DDIM / BN, DDIM / BM), 384, SMEMB>>>(out, wsc, bias);
}

// round 10
// speedup vs baseline: 1.2796x; 1.0797x over previous
#include <cuda_runtime.h>
#include <cuda_bf16.h>
#include <cstdint>

#define DDIM 4096

// Scratch (static __device__ arrays: allocation-free per harness rules)
__device__ int8_t g_q[(size_t)DDIM * DDIM];   // quantized activations, int8 in [-8,7]
__device__ int8_t g_w[(size_t)DDIM * DDIM];   // int4 weights as int8
__device__ float  g_sx[DDIM];                 // per-row activation scales (max/7)

// ---------------- PTX utility ----------------
__device__ __forceinline__ uint32_t smem_u32(const void* p) {
    uint32_t a;
    asm("{ .reg .u64 t; cvta.to.shared.u64 t, %1; cvt.u32.u64 %0, t; }" : "=r"(a) : "l"(p));
    return a;
}
__device__ __forceinline__ void cp16(uint32_t dst, const void* src) {
    asm volatile("cp.async.cg.shared.global [%0], [%1], 16;\n" :: "r"(dst), "l"(src));
}
#define CP_COMMIT() asm volatile("cp.async.commit_group;\n" ::: "memory")

__device__ __forceinline__ void barx(int id, int cnt) {
    asm volatile("bar.sync %0, %1;" :: "r"(id), "r"(cnt) : "memory");
}
__device__ __forceinline__ void ldsm4(uint32_t* r, uint32_t addr) {
    asm volatile("ldmatrix.sync.aligned.m8n8.x4.shared.b16 {%0,%1,%2,%3}, [%4];\n"
                 : "=r"(r[0]), "=r"(r[1]), "=r"(r[2]), "=r"(r[3]) : "r"(addr));
}
__device__ __forceinline__ void ldsm2(uint32_t* r, uint32_t addr) {
    asm volatile("ldmatrix.sync.aligned.m8n8.x2.shared.b16 {%0,%1}, [%2];\n"
                 : "=r"(r[0]), "=r"(r[1]) : "r"(addr));
}
__device__ __forceinline__ void imma(int* c, const uint32_t* a, uint32_t b0, uint32_t b1) {
    asm volatile(
        "mma.sync.aligned.m16n8k32.row.col.s32.s8.s8.s32 "
        "{%0,%1,%2,%3}, {%4,%5,%6,%7}, {%8,%9}, {%0,%1,%2,%3};\n"
        : "+r"(c[0]), "+r"(c[1]), "+r"(c[2]), "+r"(c[3])
        : "r"(a[0]), "r"(a[1]), "r"(a[2]), "r"(a[3]), "r"(b0), "r"(b1));
}
__device__ __forceinline__ uint4 lds128(uint32_t addr) {
    uint4 v;
    asm volatile("ld.shared.v4.b32 {%0,%1,%2,%3}, [%4];"
                 : "=r"(v.x), "=r"(v.y), "=r"(v.z), "=r"(v.w) : "r"(addr));
    return v;
}

// ============================================================================
// Kernel 1: blockwise FWHT(256) + per-row absmax + int4 quantize -> int8
// ============================================================================
__global__ void __launch_bounds__(512) had_quant_kernel(const float* __restrict__ x) {
    const int row = blockIdx.x;
    const int t = threadIdx.x;
    const int w = t >> 5, l = t & 31;

    const float* xr = x + (size_t)row * DDIM + w * 256;
    float v[8];
#pragma unroll
    for (int j = 0; j < 8; j++) v[j] = xr[j * 32 + l];

#pragma unroll
    for (int s = 0; s < 5; s++) {
        const int m = 1 << s;
        const bool hi = (l & m) != 0;
#pragma unroll
        for (int j = 0; j < 8; j++) {
            float p = __shfl_xor_sync(0xFFFFFFFFu, v[j], m);
            v[j] = hi ? (p - v[j]) : (v[j] + p);
        }
    }
#pragma unroll
    for (int s = 0; s < 3; s++) {
        const int m = 1 << s;
#pragma unroll
        for (int j = 0; j < 8; j++) {
            if (!(j & m)) {
                float a = v[j], b = v[j | m];
                v[j] = a + b;
                v[j | m] = a - b;
            }
        }
    }

    float amax = 0.0f;
#pragma unroll
    for (int j = 0; j < 8; j++) {
        v[j] *= 0.0625f;  // 1/sqrt(256)
        amax = fmaxf(amax, fabsf(v[j]));
    }
#pragma unroll
    for (int o = 16; o > 0; o >>= 1)
        amax = fmaxf(amax, __shfl_xor_sync(0xFFFFFFFFu, amax, o));

    __shared__ float smax[16];
    if (l == 0) smax[w] = amax;
    __syncthreads();
    if (t == 0) {
        float mx = smax[0];
#pragma unroll
        for (int i = 1; i < 16; i++) mx = fmaxf(mx, smax[i]);
        float sx = mx / 7.0f;
        smax[0] = sx;
        g_sx[row] = sx;
    }
    __syncthreads();
    const float sx = smax[0];

    int8_t* qr = g_q + (size_t)row * DDIM + w * 256;
#pragma unroll
    for (int j = 0; j < 8; j++) {
        float qv = rintf(v[j] / sx);              // round-half-even, matches jnp.round
        qv = fminf(fmaxf(qv, -8.0f), 7.0f);
        qr[j * 32 + l] = (int8_t)(int)qv;
    }
}

// ============================================================================
// Kernel 2: weight int32 -> int8 (values in [-7,7])
// ============================================================================
__global__ void __launch_bounds__(256) wconv_kernel(const int* __restrict__ wi) {
    const size_t i = ((size_t)blockIdx.x * blockDim.x + threadIdx.x) * 4;
    int4 a = *(const int4*)(wi + i);
    char4 c = make_char4((char)a.x, (char)a.y, (char)a.z, (char)a.w);
    *(char4*)(g_w + i) = c;
}

// ============================================================================
// Kernel 3: dual-pipe int8 GEMM, rebalanced to measured pipe rates
//   (tensor-compat ~240 MAC/cyc/SM, dp4a ~134 MAC/cyc/SM -> 80/48 col split).
//   Warps 0-7  (256 thr): mma.sync IMMA, output cols 0-79 (warp tile 32x40).
//   Warps 8-11 (128 thr): dp4a, output cols 80-127 (8x6 accs/thread).
// Independent cp.async pipelines, smem buffers, named barriers.
// SMEM rows padded to 80B (stride 20 words mod 32 banks -> conflict-free).
// ============================================================================
#define BM 128
#define BN 128
#define BK 64
#define KITERS (DDIM / BK)          // 64
#define NI 80                       // IMMA column count
#define ND 48                       // dp4a column count
#define ROWB 80                     // padded smem row stride (bytes)
#define I_ATILEB (128 * ROWB)       // 10240: A tile 128x64
#define I_BTILEB (NI * ROWB)        // 6400:  B tile 80x64
#define I_STAGEB (I_ATILEB + I_BTILEB)   // 16640
#define D_OFF (4 * I_STAGEB)        // 66560
#define D_ATILEB (128 * ROWB)       // 10240
#define D_BTILEB (ND * ROWB)        // 3840
#define D_STAGEB (D_ATILEB + D_BTILEB)   // 14080
#define SMEMB (D_OFF + 4 * D_STAGEB)     // 122880

__global__ void __launch_bounds__(384, 1)
gemm_kernel(float* __restrict__ out, const float* __restrict__ wsc,
            const float* __restrict__ bias) {
    extern __shared__ char smem[];
    const uint32_t sb = smem_u32(smem);
    const int t = threadIdx.x;
    const int mrow = blockIdx.y * BM;
    const int ncol = blockIdx.x * BN;

    if (t < 256) {
        // ================= IMMA group: cols [ncol, ncol+80) =================
        const int lane = t & 31, wid = t >> 5;
        const int wm = (wid & 3) * 32;      // warp M offset
        const int wn = (wid >> 2) * 40;     // warp N offset (0 or 40)

        const int8_t* gA = g_q + (size_t)mrow * DDIM;
        const int8_t* gB = g_w + (size_t)ncol * DDIM;

        // A: 512 chunks -> 2/thread; B: 320 chunks -> 1/thread + extra for t<64
        const int ar0 = (t * 2) >> 2, ac0 = (t * 2) & 3;   // ac0 in {0,2}
        const int br = t >> 2, bc = t & 3;
        const int br2 = 64 + (t >> 2);                      // for t < 64

        const int arow = lane & 15;
        const int ahi  = ((lane >> 4) & 1) * 16;
        const int brow = (lane & 7) + ((lane >> 4) & 1) * 8;
        const int bhi  = ((lane >> 3) & 1) * 16;
        const int b2row = lane & 7;                         // ldsm2 rows
        const int b2hi  = ((lane >> 3) & 1) * 16;

        int acc[2][5][4];
#pragma unroll
        for (int mt = 0; mt < 2; mt++)
#pragma unroll
            for (int nt = 0; nt < 5; nt++)
#pragma unroll
                for (int i = 0; i < 4; i++) acc[mt][nt][i] = 0;

#pragma unroll
        for (int s = 0; s < 3; s++) {
            const uint32_t ab = sb + s * I_STAGEB;
            cp16(ab + ar0 * ROWB + ac0 * 16, gA + (size_t)ar0 * DDIM + s * BK + ac0 * 16);
            cp16(ab + ar0 * ROWB + (ac0 + 1) * 16, gA + (size_t)ar0 * DDIM + s * BK + (ac0 + 1) * 16);
            cp16(ab + I_ATILEB + br * ROWB + bc * 16, gB + (size_t)br * DDIM + s * BK + bc * 16);
            if (t < 64)
                cp16(ab + I_ATILEB + br2 * ROWB + bc * 16, gB + (size_t)br2 * DDIM + s * BK + bc * 16);
            CP_COMMIT();
        }

        for (int it = 0; it < KITERS; it++) {
            barx(1, 256);
            if (it + 3 < KITERS) {
                const int slot = (it + 3) & 3;
                const int kb = (it + 3) * BK;
                const uint32_t ab = sb + slot * I_STAGEB;
                cp16(ab + ar0 * ROWB + ac0 * 16, gA + (size_t)ar0 * DDIM + kb + ac0 * 16);
                cp16(ab + ar0 * ROWB + (ac0 + 1) * 16, gA + (size_t)ar0 * DDIM + kb + (ac0 + 1) * 16);
                cp16(ab + I_ATILEB + br * ROWB + bc * 16, gB + (size_t)br * DDIM + kb + bc * 16);
                if (t < 64)
                    cp16(ab + I_ATILEB + br2 * ROWB + bc * 16, gB + (size_t)br2 * DDIM + kb + bc * 16);
            }
            CP_COMMIT();
            asm volatile("cp.async.wait_group 3;\n" ::: "memory");
            barx(1, 256);

            const uint32_t ab = sb + (it & 3) * I_STAGEB;
            const uint32_t bb = ab + I_ATILEB;
#pragma unroll
            for (int ks = 0; ks < 2; ks++) {
                uint32_t af[2][4];
#pragma unroll
                for (int mt = 0; mt < 2; mt++)
                    ldsm4(af[mt], ab + (wm + mt * 16 + arow) * ROWB + ks * 32 + ahi);
                uint32_t bf[10];
#pragma unroll
                for (int p = 0; p < 2; p++)
                    ldsm4(bf + p * 4, bb + (wn + p * 16 + brow) * ROWB + ks * 32 + bhi);
                ldsm2(bf + 8, bb + (wn + 32 + b2row) * ROWB + ks * 32 + b2hi);
#pragma unroll
                for (int mt = 0; mt < 2; mt++)
#pragma unroll
                    for (int nt = 0; nt < 5; nt++)
                        imma(acc[mt][nt], af[mt], bf[nt * 2], bf[nt * 2 + 1]);
            }
        }

        // fused dequant epilogue (cols 0..79 of the CTA tile)
        const int g = lane >> 2, tg = lane & 3;
#pragma unroll
        for (int mt = 0; mt < 2; mt++) {
            const int r0 = mrow + wm + mt * 16 + g;
            const float sx0 = g_sx[r0];
            const float sx1 = g_sx[r0 + 8];
            float* o0 = out + (size_t)r0 * DDIM + ncol + wn;
            float* o1 = o0 + (size_t)8 * DDIM;
#pragma unroll
            for (int nt = 0; nt < 5; nt++) {
                const int co = nt * 8 + tg * 2;
                const int col = ncol + wn + co;
                const float w0 = __ldg(wsc + col), w1 = __ldg(wsc + col + 1);
                const float b0 = __ldg(bias + col), b1 = __ldg(bias + col + 1);
                float2 v0, v1;
                v0.x = (float)acc[mt][nt][0] * sx0 * w0 + b0;
                v0.y = (float)acc[mt][nt][1] * sx0 * w1 + b1;
                v1.x = (float)acc[mt][nt][2] * sx1 * w0 + b0;
                v1.y = (float)acc[mt][nt][3] * sx1 * w1 + b1;
                *(float2*)(o0 + co) = v0;
                *(float2*)(o1 + co) = v1;
            }
        }
    } else {
        // ================= dp4a group: cols [ncol+80, ncol+128) =============
        const int t2 = t - 256;             // 0..127
        const int tx = t2 & 7;              // col group
        const int ty = t2 >> 3;             // row group 0..15

        const int8_t* gA = g_q + (size_t)mrow * DDIM;
        const int8_t* gB = g_w + (size_t)(ncol + NI) * DDIM;

        int acc[8][6];
#pragma unroll
        for (int jj = 0; jj < 8; jj++)
#pragma unroll
            for (int kk = 0; kk < 6; kk++) acc[jj][kk] = 0;

        const uint32_t dbase = sb + D_OFF;

        // A: 512 chunks -> 4/thread; B: 192 chunks -> 1/thread + extra t2<64
#pragma unroll
        for (int s = 0; s < 3; s++) {
            const uint32_t ab = dbase + s * D_STAGEB;
#pragma unroll
            for (int u = 0; u < 4; u++) {
                const int cc = t2 * 4 + u, r = cc >> 2, c = cc & 3;
                cp16(ab + r * ROWB + c * 16, gA + (size_t)r * DDIM + s * BK + c * 16);
            }
            {
                const int r = t2 >> 2, c = t2 & 3;
                cp16(ab + D_ATILEB + r * ROWB + c * 16, gB + (size_t)r * DDIM + s * BK + c * 16);
            }
            if (t2 < 64) {
                const int r = 32 + (t2 >> 2), c = t2 & 3;
                cp16(ab + D_ATILEB + r * ROWB + c * 16, gB + (size_t)r * DDIM + s * BK + c * 16);
            }
            CP_COMMIT();
        }

        for (int it = 0; it < KITERS; it++) {
            barx(2, 128);
            if (it + 3 < KITERS) {
                const int slot = (it + 3) & 3;
                const int kb = (it + 3) * BK;
                const uint32_t ab = dbase + slot * D_STAGEB;
#pragma unroll
                for (int u = 0; u < 4; u++) {
                    const int cc = t2 * 4 + u, r = cc >> 2, c = cc & 3;
                    cp16(ab + r * ROWB + c * 16, gA + (size_t)r * DDIM + kb + c * 16);
                }
                {
                    const int r = t2 >> 2, c = t2 & 3;
                    cp16(ab + D_ATILEB + r * ROWB + c * 16, gB + (size_t)r * DDIM + kb + c * 16);
                }
                if (t2 < 64) {
                    const int r = 32 + (t2 >> 2), c = t2 & 3;
                    cp16(ab + D_ATILEB + r * ROWB + c * 16, gB + (size_t)r * DDIM + kb + c * 16);
                }
            }
            CP_COMMIT();
            asm volatile("cp.async.wait_group 3;\n" ::: "memory");
            barx(2, 128);

            const uint32_t ab = dbase + (it & 3) * D_STAGEB;
            const uint32_t bb = ab + D_ATILEB;
#pragma unroll
            for (int k16 = 0; k16 < 4; k16++) {
                uint4 a4[8], b4[6];
#pragma unroll
                for (int jj = 0; jj < 8; jj++)
                    a4[jj] = lds128(ab + (ty + 16 * jj) * ROWB + k16 * 16);
#pragma unroll
                for (int kk = 0; kk < 6; kk++)
                    b4[kk] = lds128(bb + (tx + 8 * kk) * ROWB + k16 * 16);
#pragma unroll
                for (int jj = 0; jj < 8; jj++)
#pragma unroll
                    for (int kk = 0; kk < 6; kk++) {
                        int s = acc[jj][kk];
                        s = __dp4a((int)a4[jj].x, (int)b4[kk].x, s);
                        s = __dp4a((int)a4[jj].y, (int)b4[kk].y, s);
                        s = __dp4a((int)a4[jj].z, (int)b4[kk].z, s);
                        s = __dp4a((int)a4[jj].w, (int)b4[kk].w, s);
                        acc[jj][kk] = s;
                    }
            }
        }

        // fused dequant epilogue (cols 80..127 of the CTA tile)
#pragma unroll
        for (int jj = 0; jj < 8; jj++) {
            const int r = mrow + ty + 16 * jj;
            const float sx = g_sx[r];
            float* o = out + (size_t)r * DDIM + ncol + NI;
#pragma unroll
            for (int kk = 0; kk < 6; kk++) {
                const int c = tx + 8 * kk;
                const int col = ncol + NI + c;
                o[c] = (float)acc[jj][kk] * sx * __ldg(wsc + col) + __ldg(bias + col);
            }
        }
    }
}

// ============================================================================
extern "C" void kernel_launch(void* const* d_in, const int* in_sizes, int n_in,
                              void* d_out, int out_size) {
    const float* x    = (const float*)d_in[0];
    const int*   wi   = (const int*)d_in[1];
    const float* wsc  = (const float*)d_in[2];
    const float* bias = (const float*)d_in[3];
    float* out = (float*)d_out;
    (void)in_sizes; (void)n_in; (void)out_size;

    cudaFuncSetAttribute(gemm_kernel, cudaFuncAttributeMaxDynamicSharedMemorySize, SMEMB);

    had_quant_kernel<<<DDIM, 512>>>(x);
    wconv_kernel<<<(DDIM * (size_t)DDIM) / 4 / 256, 256>>>(wi);
    gemm_kernel<<<dim3(DDIM / BN, DDIM / BM), 384, SMEMB>>>(out, wsc, bias);
}